// round 10
// baseline (speedup 1.0000x reference)
#include <cuda_runtime.h>
#include <cuda_fp16.h>
#include <cuda_bf16.h>
#include <cstdint>
#include <math.h>

#define N_IN   256
#define N_OUT  64
#define TM     128            // rows per GEMM CTA
#define XS_STRIDE 72          // x tile smem stride in halves (64 k + pad)
#define WS_STRIDE 264         // W^T smem stride in halves (256 k + pad)

#define MAX_N  100000
#define MAX_E  1600000
#define SCAN_BLK 512

// Scratch
__device__ uint4    g_hh[MAX_N * 8];         // h in fp16: 64 halves = 8 uint4 per row
__device__ __half   g_wht[N_OUT * N_IN];     // W^T in fp16: [n][k]
__device__ int      g_deg[MAX_N];            // zero at module load; restored by scan_local
__device__ int      g_bsum[256];
__device__ int      g_scan_ctr;
__device__ int      g_rowptr[MAX_N + 1];
__device__ int      g_cursor[MAX_N];
__device__ uint2    g_epack[MAX_E];          // (col, val) packed per edge

// dynamic smem: xs[128][72] halves + ws[64][264] halves
#define XS_HALVES (TM * XS_STRIDE)           // 9216
#define WS_HALVES (N_OUT * WS_STRIDE)        // 16896
#define GEMM_SMEM ((XS_HALVES + WS_HALVES) * 2)   // 52224 B

// ===========================================================================
// CSR build: histogram (4 edges/thread)
// ===========================================================================
__global__ void hist_kernel(const int* __restrict__ rows, int E, int T) {
    const int t = blockIdx.x * blockDim.x + threadIdx.x;
    if (t >= T) return;
    const int e0 = t, e1 = t + T, e2 = t + 2 * T, e3 = t + 3 * T;
    int r0 = (e0 < E) ? rows[e0] : -1;
    int r1 = (e1 < E) ? rows[e1] : -1;
    int r2 = (e2 < E) ? rows[e2] : -1;
    int r3 = (e3 < E) ? rows[e3] : -1;
    if (r0 >= 0) atomicAdd(&g_deg[r0], 1);
    if (r1 >= 0) atomicAdd(&g_deg[r1], 1);
    if (r2 >= 0) atomicAdd(&g_deg[r2], 1);
    if (r3 >= 0) atomicAdd(&g_deg[r3], 1);
}

// block sums + fused last-block exclusive scan of the block sums
__global__ void __launch_bounds__(SCAN_BLK) bsum_scan_kernel(int n, int nb) {
    __shared__ int s[SCAN_BLK];
    __shared__ int is_last;
    const int t = threadIdx.x;
    const int i = blockIdx.x * SCAN_BLK + t;
    s[t] = (i < n) ? g_deg[i] : 0;
    __syncthreads();
#pragma unroll
    for (int st = SCAN_BLK / 2; st > 0; st >>= 1) {
        if (t < st) s[t] += s[t + st];
        __syncthreads();
    }
    if (t == 0) {
        g_bsum[blockIdx.x] = s[0];
        __threadfence();
        int old = atomicAdd(&g_scan_ctr, 1);
        is_last = (old == nb - 1) ? 1 : 0;
    }
    __syncthreads();
    if (is_last) {
        const int v = (t < nb) ? g_bsum[t] : 0;
        if (t < 256) s[t] = v;
        __syncthreads();
#pragma unroll
        for (int off = 1; off < 256; off <<= 1) {
            int add = (t >= off && t < 256) ? s[t - off] : 0;
            __syncthreads();
            if (t < 256) s[t] += add;
            __syncthreads();
        }
        if (t < nb) g_bsum[t] = s[t] - v;
        if (t == 0) g_scan_ctr = 0;   // reset for next call
    }
}

__global__ void __launch_bounds__(SCAN_BLK) scan_local_kernel(int n, int E) {
    __shared__ int s[SCAN_BLK];
    const int t = threadIdx.x;
    const int i = blockIdx.x * SCAN_BLK + t;
    const int v = (i < n) ? g_deg[i] : 0;
    if (i < n) g_deg[i] = 0;          // restore invariant for next call
    s[t] = v;
    __syncthreads();
#pragma unroll
    for (int off = 1; off < SCAN_BLK; off <<= 1) {
        int add = (t >= off) ? s[t - off] : 0;
        __syncthreads();
        s[t] += add;
        __syncthreads();
    }
    const int excl = s[t] - v;
    const int base = g_bsum[blockIdx.x];
    if (i < n) {
        g_rowptr[i] = base + excl;
        g_cursor[i] = base + excl;
    }
    if (i == n - 1) g_rowptr[n] = E;
}

// ===========================================================================
// W^T fp16 prep: g_wht[n][k] = fp16(W[k][n])
// ===========================================================================
__global__ void wht_kernel(const float* __restrict__ W) {
    int i = blockIdx.x * blockDim.x + threadIdx.x;
    if (i < N_OUT * N_IN) {
        const int n = i >> 8;
        const int k = i & 255;
        g_wht[i] = __float2half_rn(W[(size_t)k * N_OUT + n]);
    }
}

// ===========================================================================
// FUSED kernel: blocks [0, G_gemm) do the fp16 MMA GEMM (R7 form),
// blocks [G_gemm, G_gemm+G_fill) do the CSR fill (4 edges/thread).
// Complementary resource profiles overlap on-chip.
// ===========================================================================
__device__ __forceinline__ void gemm_body(
    const float* __restrict__ x, const float* __restrict__ b,
    int N, int gblk)
{
    extern __shared__ uint16_t smem_h[];
    uint16_t* xs = smem_h;               // [128][XS_STRIDE]
    uint16_t* ws = smem_h + XS_HALVES;   // [64][WS_STRIDE]

    const int tid  = threadIdx.x;
    const int w    = tid >> 5;
    const int lane = tid & 31;
    const int g    = lane >> 2;          // 0..7
    const int tig  = lane & 3;           // 0..3
    const int block_row = gblk * TM;

    // ---- stage W^T: 64 rows x 256 k halves, uint4 copy ----
    for (int i = tid; i < N_OUT * 32; i += 256) {
        const int n = i >> 5;
        const int j = i & 31;
        *(uint4*)&ws[n * WS_STRIDE + j * 8] = ((const uint4*)g_wht)[n * 32 + j];
    }

    float acc[8][4];
#pragma unroll
    for (int nt = 0; nt < 8; nt++)
#pragma unroll
        for (int j = 0; j < 4; j++) acc[nt][j] = 0.f;

    for (int kc = 0; kc < 4; kc++) {
        // ---- stage x chunk: 128 rows x 64 k, fp32 -> fp16 ----
#pragma unroll
        for (int p = 0; p < 8; p++) {
            const int id  = tid + p * 256;
            const int row = id >> 4;
            const int f4  = id & 15;
            int grow = block_row + row;
            if (grow >= N) grow = N - 1;                  // clamp, result unused
            float4 v = *(const float4*)(x + (size_t)grow * N_IN + kc * 64 + f4 * 4);
            __half2 h01 = __float22half2_rn(make_float2(v.x, v.y));
            __half2 h23 = __float22half2_rn(make_float2(v.z, v.w));
            uint2 pk;
            pk.x = *(const uint32_t*)&h01;
            pk.y = *(const uint32_t*)&h23;
            *(uint2*)&xs[row * XS_STRIDE + f4 * 4] = pk;
        }
        __syncthreads();

#pragma unroll
        for (int k16 = 0; k16 < 4; k16++) {
            const int kb = k16 * 16;
            const int kglob = kc * 64 + kb;

            const int r0 = (w * 16 + g) * XS_STRIDE + kb + tig * 2;
            const int r1 = (w * 16 + g + 8) * XS_STRIDE + kb + tig * 2;
            const uint32_t a0 = *(const uint32_t*)&xs[r0];
            const uint32_t a1 = *(const uint32_t*)&xs[r1];
            const uint32_t a2 = *(const uint32_t*)&xs[r0 + 8];
            const uint32_t a3 = *(const uint32_t*)&xs[r1 + 8];

#pragma unroll
            for (int nt = 0; nt < 8; nt++) {
                const int nrow = (nt * 8 + g) * WS_STRIDE + kglob + tig * 2;
                const uint32_t b0 = *(const uint32_t*)&ws[nrow];
                const uint32_t b1 = *(const uint32_t*)&ws[nrow + 8];
                asm volatile(
                    "mma.sync.aligned.m16n8k16.row.col.f32.f16.f16.f32 "
                    "{%0, %1, %2, %3}, {%4, %5, %6, %7}, {%8, %9}, "
                    "{%0, %1, %2, %3};"
                    : "+f"(acc[nt][0]), "+f"(acc[nt][1]),
                      "+f"(acc[nt][2]), "+f"(acc[nt][3])
                    : "r"(a0), "r"(a1), "r"(a2), "r"(a3), "r"(b0), "r"(b1));
            }
        }
        __syncthreads();
    }

    // ---- epilogue: bias add (fp32), convert to fp16, store to g_hh ----
    __half* hh = (__half*)g_hh;
    const int row0 = block_row + w * 16 + g;
    const int row1 = row0 + 8;
#pragma unroll
    for (int nt = 0; nt < 8; nt++) {
        const int col = nt * 8 + 2 * tig;
        const float bx = b[col], by = b[col + 1];
        if (row0 < N) {
            __half2 h = __float22half2_rn(
                make_float2(acc[nt][0] + bx, acc[nt][1] + by));
            *(uint32_t*)(hh + (size_t)row0 * N_OUT + col) = *(const uint32_t*)&h;
        }
        if (row1 < N) {
            __half2 h = __float22half2_rn(
                make_float2(acc[nt][2] + bx, acc[nt][3] + by));
            *(uint32_t*)(hh + (size_t)row1 * N_OUT + col) = *(const uint32_t*)&h;
        }
    }
}

__device__ __forceinline__ void fill_body(
    const int* __restrict__ rows, const int* __restrict__ cols,
    const float* __restrict__ vals, int E, int T, int fblk)
{
    const int t = fblk * blockDim.x + threadIdx.x;
    if (t >= T) return;
    const int e0 = t, e1 = t + T, e2 = t + 2 * T, e3 = t + 3 * T;
    int r0 = -1, r1 = -1, r2 = -1, r3 = -1;
    uint2 q0, q1, q2, q3;
    if (e0 < E) { r0 = rows[e0]; q0 = make_uint2((unsigned)cols[e0], __float_as_uint(vals[e0])); }
    if (e1 < E) { r1 = rows[e1]; q1 = make_uint2((unsigned)cols[e1], __float_as_uint(vals[e1])); }
    if (e2 < E) { r2 = rows[e2]; q2 = make_uint2((unsigned)cols[e2], __float_as_uint(vals[e2])); }
    if (e3 < E) { r3 = rows[e3]; q3 = make_uint2((unsigned)cols[e3], __float_as_uint(vals[e3])); }
    int p0 = 0, p1 = 0, p2 = 0, p3 = 0;
    if (r0 >= 0) p0 = atomicAdd(&g_cursor[r0], 1);
    if (r1 >= 0) p1 = atomicAdd(&g_cursor[r1], 1);
    if (r2 >= 0) p2 = atomicAdd(&g_cursor[r2], 1);
    if (r3 >= 0) p3 = atomicAdd(&g_cursor[r3], 1);
    if (r0 >= 0) g_epack[p0] = q0;
    if (r1 >= 0) g_epack[p1] = q1;
    if (r2 >= 0) g_epack[p2] = q2;
    if (r3 >= 0) g_epack[p3] = q3;
}

__global__ void __launch_bounds__(256) fused_gemm_fill_kernel(
    const float* __restrict__ x, const float* __restrict__ b,
    const int* __restrict__ rows, const int* __restrict__ cols,
    const float* __restrict__ vals, int N, int E, int T, int G_gemm)
{
    if ((int)blockIdx.x < G_gemm)
        gemm_body(x, b, N, blockIdx.x);
    else
        fill_body(rows, cols, vals, E, T, blockIdx.x - G_gemm);
}

// ===========================================================================
// Gather aggregation + fused ELU: out[i] = elu(sum_e val[e] * h[col[e]])
// 8 lanes per node; each lane owns 8 halves (one uint4 = 16B) of the row.
// ===========================================================================
__device__ __forceinline__ void acc_q(float* acc, float v, uint4 q) {
    float2 f;
    f = __half22float2(*(__half2*)&q.x); acc[0] += v * f.x; acc[1] += v * f.y;
    f = __half22float2(*(__half2*)&q.y); acc[2] += v * f.x; acc[3] += v * f.y;
    f = __half22float2(*(__half2*)&q.z); acc[4] += v * f.x; acc[5] += v * f.y;
    f = __half22float2(*(__half2*)&q.w); acc[6] += v * f.x; acc[7] += v * f.y;
}

__global__ void __launch_bounds__(256) gather_kernel(float* __restrict__ out, int N)
{
    const int gtid = blockIdx.x * blockDim.x + threadIdx.x;
    const int node = gtid >> 3;
    const int lane = gtid & 7;
    if (node >= N) return;

    int beg = g_rowptr[node];
    const int end = g_rowptr[node + 1];

    float acc[8];
#pragma unroll
    for (int j = 0; j < 8; j++) acc[j] = 0.f;

    for (; beg + 4 <= end; beg += 4) {
        const uint2 e0 = g_epack[beg],     e1 = g_epack[beg + 1];
        const uint2 e2 = g_epack[beg + 2], e3 = g_epack[beg + 3];
        const uint4 q0 = g_hh[(size_t)e0.x * 8 + lane];
        const uint4 q1 = g_hh[(size_t)e1.x * 8 + lane];
        const uint4 q2 = g_hh[(size_t)e2.x * 8 + lane];
        const uint4 q3 = g_hh[(size_t)e3.x * 8 + lane];
        acc_q(acc, __uint_as_float(e0.y), q0);
        acc_q(acc, __uint_as_float(e1.y), q1);
        acc_q(acc, __uint_as_float(e2.y), q2);
        acc_q(acc, __uint_as_float(e3.y), q3);
    }
    for (; beg < end; beg++) {
        const uint2 e = g_epack[beg];
        const uint4 q = g_hh[(size_t)e.x * 8 + lane];
        acc_q(acc, __uint_as_float(e.y), q);
    }

    // ELU (alpha=1)
#pragma unroll
    for (int j = 0; j < 8; j++)
        acc[j] = acc[j] > 0.f ? acc[j] : expm1f(acc[j]);

    float* o = out + (size_t)node * N_OUT + lane * 8;
    *(float4*)(o)     = make_float4(acc[0], acc[1], acc[2], acc[3]);
    *(float4*)(o + 4) = make_float4(acc[4], acc[5], acc[6], acc[7]);
}

// ===========================================================================
extern "C" void kernel_launch(void* const* d_in, const int* in_sizes, int n_in,
                              void* d_out, int out_size)
{
    const float* x  = (const float*)d_in[0];
    const int*   er = (const int*)  d_in[1];
    const int*   ec = (const int*)  d_in[2];
    const float* ev = (const float*)d_in[3];
    const float* W  = (const float*)d_in[4];
    const float* b  = (const float*)d_in[5];
    float* out = (float*)d_out;

    const int N = in_sizes[0] / N_IN;   // 100000
    const int E = in_sizes[1];          // 1600000
    const int NB = (N + SCAN_BLK - 1) / SCAN_BLK;   // 196

    static bool attr_set = false;
    if (!attr_set) {
        cudaFuncSetAttribute(fused_gemm_fill_kernel,
                             cudaFuncAttributeMaxDynamicSharedMemorySize, GEMM_SMEM);
        attr_set = true;
    }

    const int T = (E + 3) / 4;                  // fill threads, 4 edges each
    const int G_fill = (T + 255) / 256;         // 1563
    const int G_gemm = (N + TM - 1) / TM;       // 782

    // --- prep W^T (independent) + CSR degree/scan chain ---
    wht_kernel<<<(N_OUT * N_IN + 255) / 256, 256>>>(W);
    hist_kernel<<<G_fill, 256>>>(er, E, T);
    bsum_scan_kernel<<<NB, SCAN_BLK>>>(N, NB);
    scan_local_kernel<<<NB, SCAN_BLK>>>(N, E);

    // --- fused: GEMM blocks + CSR-fill blocks overlap on-chip ---
    fused_gemm_fill_kernel<<<G_gemm + G_fill, 256, GEMM_SMEM>>>(
        x, b, er, ec, ev, N, E, T, G_gemm);

    // --- out = elu(A @ h) via CSR gather ---
    {
        long long total = (long long)N * 8;
        int blocks = (int)((total + 255) / 256);
        gather_kernel<<<blocks, 256>>>(out, N);
    }
}

// round 11
// speedup vs baseline: 1.3456x; 1.3456x over previous
#include <cuda_runtime.h>
#include <cuda_fp16.h>
#include <cuda_bf16.h>
#include <cstdint>
#include <math.h>

#define N_IN   256
#define N_OUT  64
#define TM     128            // rows per GEMM CTA
#define XS_STRIDE 72          // x tile smem stride in halves (64 k + pad)
#define WS_STRIDE 264         // W^T smem stride in halves (256 k + pad)

#define MAX_N  100000
#define MAX_E  1600000
#define SCAN_BLK 512

// Scratch
__device__ uint4    g_hh[MAX_N * 8];         // h in fp16: 64 halves = 8 uint4 per row
__device__ __half   g_wht[N_OUT * N_IN];     // W^T in fp16: [n][k]
__device__ int      g_deg[MAX_N];            // zero at module load; restored by scan_local
__device__ int      g_bsum[256];
__device__ int      g_scan_ctr;
__device__ int      g_rowptr[MAX_N + 1];
__device__ int      g_cursor[MAX_N];
__device__ uint2    g_epack[MAX_E];          // (col, val) packed per edge

// dynamic smem: xs[128][72] halves + ws[64][264] halves
#define XS_HALVES (TM * XS_STRIDE)           // 9216
#define WS_HALVES (N_OUT * WS_STRIDE)        // 16896
#define GEMM_SMEM ((XS_HALVES + WS_HALVES) * 2)   // 52224 B

// ===========================================================================
// CSR build: histogram (4 edges/thread)
// ===========================================================================
__global__ void hist_kernel(const int* __restrict__ rows, int E, int T) {
    const int t = blockIdx.x * blockDim.x + threadIdx.x;
    if (t >= T) return;
    const int e0 = t, e1 = t + T, e2 = t + 2 * T, e3 = t + 3 * T;
    int r0 = (e0 < E) ? rows[e0] : -1;
    int r1 = (e1 < E) ? rows[e1] : -1;
    int r2 = (e2 < E) ? rows[e2] : -1;
    int r3 = (e3 < E) ? rows[e3] : -1;
    if (r0 >= 0) atomicAdd(&g_deg[r0], 1);
    if (r1 >= 0) atomicAdd(&g_deg[r1], 1);
    if (r2 >= 0) atomicAdd(&g_deg[r2], 1);
    if (r3 >= 0) atomicAdd(&g_deg[r3], 1);
}

// block sums + fused last-block exclusive scan of the block sums
__global__ void __launch_bounds__(SCAN_BLK) bsum_scan_kernel(int n, int nb) {
    __shared__ int s[SCAN_BLK];
    __shared__ int is_last;
    const int t = threadIdx.x;
    const int i = blockIdx.x * SCAN_BLK + t;
    s[t] = (i < n) ? g_deg[i] : 0;
    __syncthreads();
#pragma unroll
    for (int st = SCAN_BLK / 2; st > 0; st >>= 1) {
        if (t < st) s[t] += s[t + st];
        __syncthreads();
    }
    if (t == 0) {
        g_bsum[blockIdx.x] = s[0];
        __threadfence();
        int old = atomicAdd(&g_scan_ctr, 1);
        is_last = (old == nb - 1) ? 1 : 0;
    }
    __syncthreads();
    if (is_last) {
        const int v = (t < nb) ? g_bsum[t] : 0;
        if (t < 256) s[t] = v;
        __syncthreads();
#pragma unroll
        for (int off = 1; off < 256; off <<= 1) {
            int add = (t >= off && t < 256) ? s[t - off] : 0;
            __syncthreads();
            if (t < 256) s[t] += add;
            __syncthreads();
        }
        if (t < nb) g_bsum[t] = s[t] - v;
        if (t == 0) g_scan_ctr = 0;   // reset for next call
    }
}

__global__ void __launch_bounds__(SCAN_BLK) scan_local_kernel(int n, int E) {
    __shared__ int s[SCAN_BLK];
    const int t = threadIdx.x;
    const int i = blockIdx.x * SCAN_BLK + t;
    const int v = (i < n) ? g_deg[i] : 0;
    if (i < n) g_deg[i] = 0;          // restore invariant for next call
    s[t] = v;
    __syncthreads();
#pragma unroll
    for (int off = 1; off < SCAN_BLK; off <<= 1) {
        int add = (t >= off) ? s[t - off] : 0;
        __syncthreads();
        s[t] += add;
        __syncthreads();
    }
    const int excl = s[t] - v;
    const int base = g_bsum[blockIdx.x];
    if (i < n) {
        g_rowptr[i] = base + excl;
        g_cursor[i] = base + excl;
    }
    if (i == n - 1) g_rowptr[n] = E;
}

// 4 edges per thread: 4 independent atomics in flight, packed uint2 store
__global__ void fill_kernel(const int* __restrict__ rows,
                            const int* __restrict__ cols,
                            const float* __restrict__ vals, int E, int T) {
    const int t = blockIdx.x * blockDim.x + threadIdx.x;
    if (t >= T) return;
    const int e0 = t, e1 = t + T, e2 = t + 2 * T, e3 = t + 3 * T;
    int r0 = -1, r1 = -1, r2 = -1, r3 = -1;
    uint2 q0, q1, q2, q3;
    if (e0 < E) { r0 = rows[e0]; q0 = make_uint2((unsigned)cols[e0], __float_as_uint(vals[e0])); }
    if (e1 < E) { r1 = rows[e1]; q1 = make_uint2((unsigned)cols[e1], __float_as_uint(vals[e1])); }
    if (e2 < E) { r2 = rows[e2]; q2 = make_uint2((unsigned)cols[e2], __float_as_uint(vals[e2])); }
    if (e3 < E) { r3 = rows[e3]; q3 = make_uint2((unsigned)cols[e3], __float_as_uint(vals[e3])); }
    int p0 = 0, p1 = 0, p2 = 0, p3 = 0;
    if (r0 >= 0) p0 = atomicAdd(&g_cursor[r0], 1);
    if (r1 >= 0) p1 = atomicAdd(&g_cursor[r1], 1);
    if (r2 >= 0) p2 = atomicAdd(&g_cursor[r2], 1);
    if (r3 >= 0) p3 = atomicAdd(&g_cursor[r3], 1);
    if (r0 >= 0) g_epack[p0] = q0;
    if (r1 >= 0) g_epack[p1] = q1;
    if (r2 >= 0) g_epack[p2] = q2;
    if (r3 >= 0) g_epack[p3] = q3;
}

// ===========================================================================
// W^T fp16 prep: g_wht[n][k] = fp16(W[k][n])
// ===========================================================================
__global__ void wht_kernel(const float* __restrict__ W) {
    int i = blockIdx.x * blockDim.x + threadIdx.x;
    if (i < N_OUT * N_IN) {
        const int n = i >> 8;
        const int k = i & 255;
        g_wht[i] = __float2half_rn(W[(size_t)k * N_OUT + n]);
    }
}

// ===========================================================================
// GEMM via mma.sync m16n8k16 fp16 (fp32 accum): h[N,64] = x[N,256]@W + b
// (R7 form — the best-measured GEMM configuration.)
// ===========================================================================
__global__ void __launch_bounds__(256) gemm_mma_kernel(
    const float* __restrict__ x, const float* __restrict__ b, int N)
{
    extern __shared__ uint16_t smem_h[];
    uint16_t* xs = smem_h;               // [128][XS_STRIDE]
    uint16_t* ws = smem_h + XS_HALVES;   // [64][WS_STRIDE]

    const int tid  = threadIdx.x;
    const int w    = tid >> 5;
    const int lane = tid & 31;
    const int g    = lane >> 2;          // 0..7
    const int tig  = lane & 3;           // 0..3
    const int block_row = blockIdx.x * TM;

    // ---- stage W^T: 64 rows x 256 k halves, uint4 copy ----
    for (int i = tid; i < N_OUT * 32; i += 256) {
        const int n = i >> 5;
        const int j = i & 31;
        *(uint4*)&ws[n * WS_STRIDE + j * 8] = ((const uint4*)g_wht)[n * 32 + j];
    }

    float acc[8][4];
#pragma unroll
    for (int nt = 0; nt < 8; nt++)
#pragma unroll
        for (int j = 0; j < 4; j++) acc[nt][j] = 0.f;

    for (int kc = 0; kc < 4; kc++) {
        // ---- stage x chunk: 128 rows x 64 k, fp32 -> fp16 ----
#pragma unroll
        for (int p = 0; p < 8; p++) {
            const int id  = tid + p * 256;
            const int row = id >> 4;
            const int f4  = id & 15;
            int grow = block_row + row;
            if (grow >= N) grow = N - 1;                  // clamp, result unused
            float4 v = *(const float4*)(x + (size_t)grow * N_IN + kc * 64 + f4 * 4);
            __half2 h01 = __float22half2_rn(make_float2(v.x, v.y));
            __half2 h23 = __float22half2_rn(make_float2(v.z, v.w));
            uint2 pk;
            pk.x = *(const uint32_t*)&h01;
            pk.y = *(const uint32_t*)&h23;
            *(uint2*)&xs[row * XS_STRIDE + f4 * 4] = pk;
        }
        __syncthreads();

#pragma unroll
        for (int k16 = 0; k16 < 4; k16++) {
            const int kb = k16 * 16;
            const int kglob = kc * 64 + kb;

            const int r0 = (w * 16 + g) * XS_STRIDE + kb + tig * 2;
            const int r1 = (w * 16 + g + 8) * XS_STRIDE + kb + tig * 2;
            const uint32_t a0 = *(const uint32_t*)&xs[r0];
            const uint32_t a1 = *(const uint32_t*)&xs[r1];
            const uint32_t a2 = *(const uint32_t*)&xs[r0 + 8];
            const uint32_t a3 = *(const uint32_t*)&xs[r1 + 8];

#pragma unroll
            for (int nt = 0; nt < 8; nt++) {
                const int nrow = (nt * 8 + g) * WS_STRIDE + kglob + tig * 2;
                const uint32_t b0 = *(const uint32_t*)&ws[nrow];
                const uint32_t b1 = *(const uint32_t*)&ws[nrow + 8];
                asm volatile(
                    "mma.sync.aligned.m16n8k16.row.col.f32.f16.f16.f32 "
                    "{%0, %1, %2, %3}, {%4, %5, %6, %7}, {%8, %9}, "
                    "{%0, %1, %2, %3};"
                    : "+f"(acc[nt][0]), "+f"(acc[nt][1]),
                      "+f"(acc[nt][2]), "+f"(acc[nt][3])
                    : "r"(a0), "r"(a1), "r"(a2), "r"(a3), "r"(b0), "r"(b1));
            }
        }
        __syncthreads();
    }

    // ---- epilogue: bias add (fp32), convert to fp16, store to g_hh ----
    __half* hh = (__half*)g_hh;
    const int row0 = block_row + w * 16 + g;
    const int row1 = row0 + 8;
#pragma unroll
    for (int nt = 0; nt < 8; nt++) {
        const int col = nt * 8 + 2 * tig;
        const float bx = b[col], by = b[col + 1];
        if (row0 < N) {
            __half2 h = __float22half2_rn(
                make_float2(acc[nt][0] + bx, acc[nt][1] + by));
            *(uint32_t*)(hh + (size_t)row0 * N_OUT + col) = *(const uint32_t*)&h;
        }
        if (row1 < N) {
            __half2 h = __float22half2_rn(
                make_float2(acc[nt][2] + bx, acc[nt][3] + by));
            *(uint32_t*)(hh + (size_t)row1 * N_OUT + col) = *(const uint32_t*)&h;
        }
    }
}

// ===========================================================================
// Gather aggregation + fused ELU: out[i] = elu(sum_e val[e] * h[col[e]])
// 8 lanes per node; each lane owns 8 halves (one uint4 = 16B) of the row.
// ===========================================================================
__device__ __forceinline__ void acc_q(float* acc, float v, uint4 q) {
    float2 f;
    f = __half22float2(*(__half2*)&q.x); acc[0] += v * f.x; acc[1] += v * f.y;
    f = __half22float2(*(__half2*)&q.y); acc[2] += v * f.x; acc[3] += v * f.y;
    f = __half22float2(*(__half2*)&q.z); acc[4] += v * f.x; acc[5] += v * f.y;
    f = __half22float2(*(__half2*)&q.w); acc[6] += v * f.x; acc[7] += v * f.y;
}

__global__ void __launch_bounds__(256) gather_kernel(float* __restrict__ out, int N)
{
    const int gtid = blockIdx.x * blockDim.x + threadIdx.x;
    const int node = gtid >> 3;
    const int lane = gtid & 7;
    if (node >= N) return;

    int beg = g_rowptr[node];
    const int end = g_rowptr[node + 1];

    float acc[8];
#pragma unroll
    for (int j = 0; j < 8; j++) acc[j] = 0.f;

    for (; beg + 4 <= end; beg += 4) {
        const uint2 e0 = g_epack[beg],     e1 = g_epack[beg + 1];
        const uint2 e2 = g_epack[beg + 2], e3 = g_epack[beg + 3];
        const uint4 q0 = g_hh[(size_t)e0.x * 8 + lane];
        const uint4 q1 = g_hh[(size_t)e1.x * 8 + lane];
        const uint4 q2 = g_hh[(size_t)e2.x * 8 + lane];
        const uint4 q3 = g_hh[(size_t)e3.x * 8 + lane];
        acc_q(acc, __uint_as_float(e0.y), q0);
        acc_q(acc, __uint_as_float(e1.y), q1);
        acc_q(acc, __uint_as_float(e2.y), q2);
        acc_q(acc, __uint_as_float(e3.y), q3);
    }
    for (; beg < end; beg++) {
        const uint2 e = g_epack[beg];
        const uint4 q = g_hh[(size_t)e.x * 8 + lane];
        acc_q(acc, __uint_as_float(e.y), q);
    }

    // ELU (alpha=1)
#pragma unroll
    for (int j = 0; j < 8; j++)
        acc[j] = acc[j] > 0.f ? acc[j] : expm1f(acc[j]);

    float* o = out + (size_t)node * N_OUT + lane * 8;
    *(float4*)(o)     = make_float4(acc[0], acc[1], acc[2], acc[3]);
    *(float4*)(o + 4) = make_float4(acc[4], acc[5], acc[6], acc[7]);
}

// ===========================================================================
extern "C" void kernel_launch(void* const* d_in, const int* in_sizes, int n_in,
                              void* d_out, int out_size)
{
    const float* x  = (const float*)d_in[0];
    const int*   er = (const int*)  d_in[1];
    const int*   ec = (const int*)  d_in[2];
    const float* ev = (const float*)d_in[3];
    const float* W  = (const float*)d_in[4];
    const float* b  = (const float*)d_in[5];
    float* out = (float*)d_out;

    const int N = in_sizes[0] / N_IN;   // 100000
    const int E = in_sizes[1];          // 1600000
    const int NB = (N + SCAN_BLK - 1) / SCAN_BLK;   // 196

    // one-time infrastructure (attrs, side stream, fork/join events)
    static cudaStream_t s1;
    static cudaEvent_t ev_fork, ev_join;
    static bool init_done = false;
    if (!init_done) {
        cudaFuncSetAttribute(gemm_mma_kernel,
                             cudaFuncAttributeMaxDynamicSharedMemorySize, GEMM_SMEM);
        cudaStreamCreateWithFlags(&s1, cudaStreamNonBlocking);
        cudaEventCreateWithFlags(&ev_fork, cudaEventDisableTiming);
        cudaEventCreateWithFlags(&ev_join, cudaEventDisableTiming);
        init_done = true;
    }

    const int T = (E + 3) / 4;                  // 4 edges per thread
    const int EB = (T + 255) / 256;             // blocks for hist/fill

    // ---- fork: GEMM branch on side stream s1 ----
    cudaEventRecord(ev_fork, 0);
    cudaStreamWaitEvent(s1, ev_fork, 0);
    wht_kernel<<<(N_OUT * N_IN + 255) / 256, 256, 0, s1>>>(W);
    gemm_mma_kernel<<<(N + TM - 1) / TM, 256, GEMM_SMEM, s1>>>(x, b, N);
    cudaEventRecord(ev_join, s1);

    // ---- CSR branch on the capture (default) stream ----
    hist_kernel<<<EB, 256>>>(er, E, T);
    bsum_scan_kernel<<<NB, SCAN_BLK>>>(N, NB);
    scan_local_kernel<<<NB, SCAN_BLK>>>(N, E);
    fill_kernel<<<EB, 256>>>(er, ec, ev, E, T);

    // ---- join, then gather (needs both h and CSR) ----
    cudaStreamWaitEvent(0, ev_join, 0);
    {
        long long total = (long long)N * 8;
        int blocks = (int)((total + 255) / 256);
        gather_kernel<<<blocks, 256>>>(out, N);
    }
}